// round 6
// baseline (speedup 1.0000x reference)
#include <cuda_runtime.h>
#include <cuda_fp16.h>
#include <cstdint>

// ============================================================================
// DenseAttention via Gram reassociation:
//   G[b,q]  = X_{b,q}^T X_{b,q}             (symmetric => compute 3 of 4 tiles)
//   T[b,a,q]= (1024*W_{a,q}) @ G[b,q]
//   Pq^T    = (1024*C_{a,q})-layout @ T^T ;  P^T[b,a] = 2^-10 * sum_q Pq^T
//   out     = 2^-10 * X_{b,a} @ P[b,a]
// fp16 2-pass split: B = Bh + Bl, A = Ah:  A*B ~= Ah*Bh + Ah*Bl  (fp32 accum)
// R6: 128-thread CTAs / 64x128 tiles => 2 CTAs per SM (barrier overlap).
// ============================================================================

#define HH 65536

// ---------------- scratch (static device globals; no allocation) ------------
__device__ __align__(256) __half g_Xt_h[8 * 256 * 2048];    // [bq][f][t]
__device__ __align__(256) __half g_Xt_l[8 * 256 * 2048];
__device__ __align__(256) __half g_Xnt_h[2 * 2048 * 1024];  // [b][t][e]
__device__ __align__(256) __half g_Wc_h[16 * HH];           // [aq][e][f] *1024
__device__ __align__(256) __half g_Ct_h[16 * HH];           // [aq][g'][g] *1024
__device__ __align__(256) float  g_Gpart[4 * 8 * 3 * 16384];// [chunk][bq][tile]
__device__ __align__(256) __half g_Gh[8 * HH];              // [bq][f][g]
__device__ __align__(256) __half g_Gl[8 * HH];
__device__ __align__(256) __half g_Th[32 * HH];             // [baq][e][g]
__device__ __align__(256) __half g_Tl[32 * HH];
__device__ __align__(256) float  g_Pq[32 * HH];             // [baq][g'][e]
__device__ __align__(256) __half g_Pt_h[8 * HH];            // [ba][g'][e]
__device__ __align__(256) __half g_Pt_l[8 * HH];

// ---------------- PTX helpers ------------------------------------------------
__device__ __forceinline__ uint32_t smem_u32(const void* p) {
    uint32_t a;
    asm("{ .reg .u64 t; cvta.to.shared.u64 t, %1; cvt.u32.u64 %0, t; }" : "=r"(a) : "l"(p));
    return a;
}
__device__ __forceinline__ void cpa16(uint32_t s, const void* g) {
    asm volatile("cp.async.cg.shared.global [%0], [%1], 16;" :: "r"(s), "l"(g));
}
#define CP_COMMIT() asm volatile("cp.async.commit_group;" ::: "memory")
#define CP_WAIT(n)  asm volatile("cp.async.wait_group %0;" :: "n"(n) : "memory")

#define LDSM_X4(r, addr) \
    asm volatile("ldmatrix.sync.aligned.m8n8.x4.shared.b16 {%0,%1,%2,%3}, [%4];" \
        : "=r"((r)[0]), "=r"((r)[1]), "=r"((r)[2]), "=r"((r)[3]) : "r"(addr))

#define MMA_F16(d, a, b0, b1) \
    asm volatile("mma.sync.aligned.m16n8k16.row.col.f32.f16.f16.f32 " \
        "{%0,%1,%2,%3}, {%4,%5,%6,%7}, {%8,%9}, {%0,%1,%2,%3};" \
        : "+f"((d)[0]), "+f"((d)[1]), "+f"((d)[2]), "+f"((d)[3]) \
        : "r"((a)[0]), "r"((a)[1]), "r"((a)[2]), "r"((a)[3]), "r"(b0), "r"(b1))

// ---------------- split helpers ----------------------------------------------
__device__ __forceinline__ void splitH(float x, __half& h, __half& l) {
    h = __float2half_rn(x);
    l = __float2half_rn(x - __half2float(h));
}
__device__ __forceinline__ void split4H(float4 v, uint2& uh, uint2& ul) {
    union { __half b[4]; uint2 u; } Hq, Lq;
    float f[4] = {v.x, v.y, v.z, v.w};
#pragma unroll
    for (int i = 0; i < 4; i++) splitH(f[i], Hq.b[i], Lq.b[i]);
    uh = Hq.u; ul = Lq.u;
}
__device__ __forceinline__ uint2 pack4H(float4 v) {
    union { __half b[4]; uint2 u; } Hq;
    Hq.b[0] = __float2half_rn(v.x); Hq.b[1] = __float2half_rn(v.y);
    Hq.b[2] = __float2half_rn(v.z); Hq.b[3] = __float2half_rn(v.w);
    return Hq.u;
}

// ============================================================================
// 64x128 tile GEMM, 128 threads (4 warps: 2M x 2N, warp tile 32x64).
// K multiple of 64, double-buffered cp.async, fp16 2-pass (B = hi + lo).
// EPI 0: fp32*scale -> Cf.   EPI 1: fp16 hi/lo -> Ch/Cl.
// SMEM/buffer: A 64x144B = 9216, Bh 128x144B = 18432, Bl 18432 => 46080.
// Two buffers = 92160 B/CTA => 2 CTAs/SM.
// ============================================================================
#define ROWB   144
#define T_A_H  0
#define T_B_H  9216
#define T_B_L  27648
#define BUFSZ  46080
#define SMEM_DYN (2 * BUFSZ)

template <int EPI>
__device__ __forceinline__ void gemm_body(
    const __half* __restrict__ Ah, int lda,
    const __half* __restrict__ Bh, const __half* __restrict__ Bl, int ldb,
    int K, float* __restrict__ Cf,
    __half* __restrict__ Ch, __half* __restrict__ Cl, int ldc, float outScale)
{
    extern __shared__ char smem[];
    const uint32_t sb  = smem_u32(smem);
    const int tid  = threadIdx.x;
    const int lane = tid & 31;
    const int wid  = tid >> 5;
    const int m0   = (wid >> 1) * 32;   // 0 or 32
    const int n0   = (wid & 1) * 64;    // 0 or 64

    const uint32_t aoff = (uint32_t)(m0 + (lane & 15)) * ROWB + ((lane >> 4) << 4);
    const uint32_t boff = (uint32_t)(n0 + ((lane >> 4) << 3) + (lane & 7)) * ROWB
                        + ((lane & 8) ? 16u : 0u);

    float acc[2][8][4];
#pragma unroll
    for (int i = 0; i < 2; i++)
#pragma unroll
        for (int j = 0; j < 8; j++)
#pragma unroll
            for (int r = 0; r < 4; r++) acc[i][j][r] = 0.0f;

    auto load_chunk = [&](int c) {
        const uint32_t bo = sb + (uint32_t)(c & 1) * BUFSZ;
        const int k0 = c << 6;
        // A: 64 rows x 8 vec16 = 512 -> 4 iters of 128 threads
#pragma unroll
        for (int i = 0; i < 4; i++) {
            int v = i * 128 + tid;
            int r = v >> 3, j = v & 7;
            uint32_t so = (uint32_t)r * ROWB + (uint32_t)j * 16;
            cpa16(bo + T_A_H + so, Ah + (size_t)r * lda + k0 + j * 8);
        }
        // B: 128 rows x 8 vec16 = 1024 -> 8 iters, hi + lo
#pragma unroll
        for (int i = 0; i < 8; i++) {
            int v = i * 128 + tid;
            int r = v >> 3, j = v & 7;
            uint32_t so = (uint32_t)r * ROWB + (uint32_t)j * 16;
            cpa16(bo + T_B_H + so, Bh + (size_t)r * ldb + k0 + j * 8);
            cpa16(bo + T_B_L + so, Bl + (size_t)r * ldb + k0 + j * 8);
        }
    };

    const int NC = K >> 6;
    load_chunk(0);
    CP_COMMIT();

#pragma unroll 1
    for (int c = 0; c < NC; c++) {
        if (c < NC - 1) { load_chunk(c + 1); CP_COMMIT(); CP_WAIT(1); }
        else            { CP_WAIT(0); }
        __syncthreads();

        const uint32_t bo = sb + (uint32_t)(c & 1) * BUFSZ;
        const uint32_t aH = bo + T_A_H + aoff;
        const uint32_t bH = bo + T_B_H + boff;
        const uint32_t bL = bo + T_B_L + boff;

#pragma unroll
        for (int ks = 0; ks < 4; ks++) {
            const uint32_t ko = (uint32_t)ks * 32;
            uint32_t ah0[4], ah1[4];
            LDSM_X4(ah0, aH + ko);
            LDSM_X4(ah1, aH + 16 * ROWB + ko);
            uint32_t bhr[4][4], blr[4][4];
#pragma unroll
            for (int p = 0; p < 4; p++) {
                LDSM_X4(bhr[p], bH + (uint32_t)p * 16 * ROWB + ko);
                LDSM_X4(blr[p], bL + (uint32_t)p * 16 * ROWB + ko);
            }
#pragma unroll
            for (int j = 0; j < 8; j++)
                MMA_F16(acc[0][j], ah0, bhr[j >> 1][(j & 1) * 2], bhr[j >> 1][(j & 1) * 2 + 1]);
#pragma unroll
            for (int j = 0; j < 8; j++)
                MMA_F16(acc[1][j], ah1, bhr[j >> 1][(j & 1) * 2], bhr[j >> 1][(j & 1) * 2 + 1]);
#pragma unroll
            for (int j = 0; j < 8; j++)
                MMA_F16(acc[0][j], ah0, blr[j >> 1][(j & 1) * 2], blr[j >> 1][(j & 1) * 2 + 1]);
#pragma unroll
            for (int j = 0; j < 8; j++)
                MMA_F16(acc[1][j], ah1, blr[j >> 1][(j & 1) * 2], blr[j >> 1][(j & 1) * 2 + 1]);
        }
        __syncthreads();
    }

    // ---- epilogue ----
    const int rr = lane >> 2;
    const int cc = (lane & 3) * 2;
#pragma unroll
    for (int i = 0; i < 2; i++) {
#pragma unroll
        for (int j = 0; j < 8; j++) {
            const int row = m0 + i * 16 + rr;
            const int col = n0 + j * 8 + cc;
            if (EPI == 0) {
                float* p = Cf + (size_t)row * ldc + col;
                *(float2*)p = make_float2(acc[i][j][0] * outScale, acc[i][j][1] * outScale);
                *(float2*)(p + (size_t)8 * ldc) =
                    make_float2(acc[i][j][2] * outScale, acc[i][j][3] * outScale);
            } else {
                __half h0, l0, h1, l1;
                splitH(acc[i][j][0], h0, l0); splitH(acc[i][j][1], h1, l1);
                *(__half2*)(Ch + (size_t)row * ldc + col) = __halves2half2(h0, h1);
                *(__half2*)(Cl + (size_t)row * ldc + col) = __halves2half2(l0, l1);
                splitH(acc[i][j][2], h0, l0); splitH(acc[i][j][3], h1, l1);
                *(__half2*)(Ch + (size_t)(row + 8) * ldc + col) = __halves2half2(h0, h1);
                *(__half2*)(Cl + (size_t)(row + 8) * ldc + col) = __halves2half2(l0, l1);
            }
        }
    }
}

// ============================================================================
// fused conversion kernel: grid 6144 blocks x 256
//   [0,4096)     : hidden tile -> Xt hi/lo (transposed) AND Xnt hi (natural)
//   [4096,5120)  : Wc hi *1024
//   [5120,6144)  : Ct hi *1024 (transposed)
// ============================================================================
__global__ void k_conv(const float* __restrict__ hid,
                       const float* __restrict__ qr,
                       const float* __restrict__ cb)
{
    __shared__ float ts[32][33];
    const int blk = blockIdx.x;
    const int tid = threadIdx.x;

    if (blk < 4096) {
        int i = blk;                                     // 8 x 64 x 8
        int fb = i & 7, tb = (i >> 3) & 63, bq = i >> 9;
        int b = bq >> 2, q = bq & 3;
        int t0 = tb * 32, f0 = fb * 32;
        int tx = tid & 31, ty = tid >> 5;
#pragma unroll
        for (int r = 0; r < 4; r++) {
            int tt = t0 + ty + r * 8;
            float v = hid[(size_t)b * 2097152 + (size_t)tt * 1024 + q * 256 + f0 + tx];
            ts[ty + r * 8][tx] = v;
            g_Xnt_h[(size_t)b * 2097152 + (size_t)tt * 1024 + q * 256 + f0 + tx] =
                __float2half_rn(v);
        }
        __syncthreads();
#pragma unroll
        for (int r = 0; r < 4; r++) {
            int f = f0 + ty + r * 8;
            int tw = t0 + tx;
            __half h, l;
            splitH(ts[tx][ty + r * 8], h, l);
            size_t o = (size_t)bq * 524288 + (size_t)f * 2048 + tw;
            g_Xt_h[o] = h; g_Xt_l[o] = l;
        }
    } else if (blk < 5120) {
        int o4 = (blk - 4096) * 256 + tid;               // 262144 float4s
        int aq = o4 >> 14;
        int rem = (o4 << 2) & 65535;
        int e = rem >> 8, f = rem & 255;
        int a = aq >> 2, q = aq & 3;
        float4 v = *(const float4*)(qr + (size_t)a * 262144 + (size_t)e * 1024 + q * 256 + f);
        v.x *= 1024.f; v.y *= 1024.f; v.z *= 1024.f; v.w *= 1024.f;
        ((uint2*)g_Wc_h)[o4] = pack4H(v);
    } else {
        int i = blk - 5120;                              // 8 x 8 x 16
        int gpb = i & 7, gb = (i >> 3) & 7, aq = i >> 6;
        int a = aq >> 2, q = aq & 3;
        int g0 = gb * 32, gp0 = gpb * 32;
        int tx = tid & 31, ty = tid >> 5;
#pragma unroll
        for (int r = 0; r < 4; r++) {
            int g = g0 + ty + r * 8;
            ts[ty + r * 8][tx] =
                cb[(size_t)a * 262144 + (size_t)(q * 256 + g) * 256 + gp0 + tx] * 1024.f;
        }
        __syncthreads();
#pragma unroll
        for (int r = 0; r < 4; r++) {
            int gp = gp0 + ty + r * 8;
            int gw = g0 + tx;
            g_Ct_h[(size_t)aq * 65536 + (size_t)gp * 256 + gw] =
                __float2half_rn(ts[tx][ty + r * 8]);
        }
    }
}

// ---- reduce Gram partials (4 chunks, 3 tiles) + mirror + split fp16 ---------
__global__ void k_reduceG()
{
    __shared__ float s[32][33];
    const int sub = blockIdx.x, t = blockIdx.y, bq = blockIdx.z;
    const int r0 = (sub >> 2) * 32, c0 = (sub & 3) * 32;
    const int tx = threadIdx.x & 31, ty = threadIdx.x >> 5;

    const int br = (t == 2) ? 128 : 0;
    const int bc = (t == 0) ? 0 : 128;
    float v[4];
#pragma unroll
    for (int k = 0; k < 4; k++) {
        const int r = r0 + ty + k * 8;
        float a = 0.f;
#pragma unroll
        for (int ch = 0; ch < 4; ch++)
            a += g_Gpart[(size_t)((ch * 8 + bq) * 3 + t) * 16384 + r * 128 + c0 + tx];
        v[k] = a;
        s[ty + k * 8][tx] = a;
    }
#pragma unroll
    for (int k = 0; k < 4; k++) {
        __half h, l;
        splitH(v[k], h, l);
        size_t o = (size_t)bq * 65536 + (size_t)(br + r0 + ty + k * 8) * 256 + bc + c0 + tx;
        g_Gh[o] = h; g_Gl[o] = l;
    }
    if (t == 1) {
        __syncthreads();
#pragma unroll
        for (int k = 0; k < 4; k++) {
            const int orow = 128 + c0 + ty + k * 8;
            const int ocol = r0 + tx;
            __half h, l;
            splitH(s[tx][ty + k * 8], h, l);
            size_t o = (size_t)bq * 65536 + (size_t)orow * 256 + ocol;
            g_Gh[o] = h; g_Gl[o] = l;
        }
    }
}

// ---- reduce Pq^T over q, descale 2^-10, split fp16 hi/lo --------------------
__global__ void k_reduceP()
{
    int i4 = blockIdx.x * 256 + threadIdx.x;
    int ba = i4 >> 14;
    int off = i4 & 16383;
    int b = ba >> 2, a = ba & 3;
    size_t base = (size_t)(b * 16 + a * 4) * 16384 + off;
    float4 s = make_float4(0.f, 0.f, 0.f, 0.f);
#pragma unroll
    for (int q = 0; q < 4; q++) {
        float4 v = ((const float4*)g_Pq)[base + (size_t)q * 16384];
        s.x += v.x; s.y += v.y; s.z += v.z; s.w += v.w;
    }
    const float ds = 1.0f / 1024.0f;
    s.x *= ds; s.y *= ds; s.z *= ds; s.w *= ds;
    uint2 uh, ul;
    split4H(s, uh, ul);
    ((uint2*)g_Pt_h)[i4] = uh;
    ((uint2*)g_Pt_l)[i4] = ul;
}

// ============================================================================
// GEMM stage kernels (all 128-thread CTAs, 64x128 tiles)
// ============================================================================
__global__ void __launch_bounds__(128, 2)
k_s1()  // Gram, symmetric: grid (x = t*2+h : 6, chunk 4, bq 8) = 192 CTAs, K=512
{
    const int t  = blockIdx.x >> 1;            // 0:(0,0) 1:(0,1) 2:(1,1)
    const int h  = blockIdx.x & 1;             // which 64-row half
    const int ch = blockIdx.y, bq = blockIdx.z;
    const int mt = (t == 2) ? 1 : 0;
    const int nt = (t == 0) ? 0 : 1;
    const int k0 = ch * 512;

    size_t xo = (size_t)bq * 524288;
    const __half* Ah = g_Xt_h + xo + (size_t)(mt * 128 + h * 64) * 2048 + k0;
    const __half* Bh = g_Xt_h + xo + (size_t)nt * 128 * 2048 + k0;
    const __half* Bl = g_Xt_l + xo + (size_t)nt * 128 * 2048 + k0;
    float* Cf = g_Gpart + (size_t)((ch * 8 + bq) * 3 + t) * 16384 + (size_t)h * 64 * 128;
    gemm_body<0>(Ah, 2048, Bh, Bl, 2048, 512, Cf, nullptr, nullptr, 128, 1.0f);
}

__global__ void __launch_bounds__(128, 2)
k_s2()  // T = Ws @ G: grid (8, 1, 32) = 256 CTAs
{
    int mt = blockIdx.x >> 1, nt = blockIdx.x & 1;   // mt: 0..3 (64-row), nt: 0..1
    int baq = blockIdx.z;
    int b = baq >> 4, a = (baq >> 2) & 3, q = baq & 3;
    const __half* Ah = g_Wc_h + (size_t)(a * 4 + q) * 65536 + (size_t)mt * 64 * 256;
    const __half* Bh = g_Gh + (size_t)(b * 4 + q) * 65536 + (size_t)nt * 128 * 256;
    const __half* Bl = g_Gl + (size_t)(b * 4 + q) * 65536 + (size_t)nt * 128 * 256;
    __half* Ch = g_Th + (size_t)baq * 65536 + (size_t)mt * 64 * 256 + nt * 128;
    __half* Cl = g_Tl + (size_t)baq * 65536 + (size_t)mt * 64 * 256 + nt * 128;
    gemm_body<1>(Ah, 256, Bh, Bl, 256, 256, nullptr, Ch, Cl, 256, 1.0f);
}

__global__ void __launch_bounds__(128, 2)
k_s3()  // Pq^T = Cs_t @ T^T: grid (8, 1, 32) = 256 CTAs
{
    int mt = blockIdx.x >> 1, nt = blockIdx.x & 1;
    int baq = blockIdx.z;
    int a = (baq >> 2) & 3, q = baq & 3;
    const __half* Ah = g_Ct_h + (size_t)(a * 4 + q) * 65536 + (size_t)mt * 64 * 256;
    const __half* Bh = g_Th + (size_t)baq * 65536 + (size_t)nt * 128 * 256;
    const __half* Bl = g_Tl + (size_t)baq * 65536 + (size_t)nt * 128 * 256;
    float* Cf = g_Pq + (size_t)baq * 65536 + (size_t)mt * 64 * 256 + nt * 128;
    gemm_body<0>(Ah, 256, Bh, Bl, 256, 256, Cf, nullptr, nullptr, 256, 1.0f);
}

__global__ void __launch_bounds__(128, 2)
k_s4(float* __restrict__ out)  // out = 2^-10 * X @ P: grid (64, 1, 8) = 512 CTAs
{
    int mt = blockIdx.x >> 1, nt = blockIdx.x & 1;   // mt: 0..31 (64-row)
    int ba = blockIdx.z;
    int b = ba >> 2, a = ba & 3;
    const __half* Ah = g_Xnt_h + (size_t)b * 2097152 + (size_t)mt * 64 * 1024 + a * 256;
    const __half* Bh = g_Pt_h + (size_t)ba * 65536 + (size_t)nt * 128 * 256;
    const __half* Bl = g_Pt_l + (size_t)ba * 65536 + (size_t)nt * 128 * 256;
    float* Cf = out + (size_t)b * 2097152 + (size_t)mt * 64 * 1024 + a * 256 + nt * 128;
    gemm_body<0>(Ah, 1024, Bh, Bl, 256, 256, Cf, nullptr, nullptr, 1024, 1.0f / 1024.0f);
}

// ============================================================================
extern "C" void kernel_launch(void* const* d_in, const int* in_sizes, int n_in,
                              void* d_out, int out_size)
{
    const float* hidden    = (const float*)d_in[0];  // [2,2048,1024]
    const float* queries   = (const float*)d_in[1];  // [4,256,1024]
    const float* combiners = (const float*)d_in[2];  // [4,1024,256]
    float* out = (float*)d_out;
    (void)in_sizes; (void)n_in; (void)out_size;

    cudaFuncSetAttribute(k_s1, cudaFuncAttributeMaxDynamicSharedMemorySize, SMEM_DYN);
    cudaFuncSetAttribute(k_s2, cudaFuncAttributeMaxDynamicSharedMemorySize, SMEM_DYN);
    cudaFuncSetAttribute(k_s3, cudaFuncAttributeMaxDynamicSharedMemorySize, SMEM_DYN);
    cudaFuncSetAttribute(k_s4, cudaFuncAttributeMaxDynamicSharedMemorySize, SMEM_DYN);

    k_conv<<<6144, 256>>>(hidden, queries, combiners);
    k_s1<<<dim3(6, 4, 8), 128, SMEM_DYN>>>();
    k_reduceG<<<dim3(16, 3, 8), 256>>>();
    k_s2<<<dim3(8, 1, 32), 128, SMEM_DYN>>>();
    k_s3<<<dim3(8, 1, 32), 128, SMEM_DYN>>>();
    k_reduceP<<<512, 256>>>();
    k_s4<<<dim3(64, 1, 8), 128, SMEM_DYN>>>(out);
}

// round 7
// speedup vs baseline: 1.5975x; 1.5975x over previous
#include <cuda_runtime.h>
#include <cuda_fp16.h>
#include <cstdint>

// ============================================================================
// DenseAttention via Gram reassociation:
//   G[b,q]  = X_{b,q}^T X_{b,q}             (symmetric => compute 3 of 4 tiles)
//   T[b,a,q]= (1024*W_{a,q}) @ G[b,q]
//   Pq^T    = (1024*C_{a,q})-layout @ T^T ;  P^T[b,a] = 2^-10 * sum_q Pq^T
//   out     = 2^-10 * X_{b,a} @ P[b,a]
// R7: single-pass fp16 (hi only), fp32 accumulate. Tensor pipe is saturated at
// the mma.sync fallback ceiling, so fewer MMAs is the only lever: halves work.
// Predicted rel_err ~5e-4 (calibrated from R4/R5's 3.66e-4 with one extra
// dropped cross-term per stage).
// ============================================================================

#define HH 65536

// ---------------- scratch (static device globals; no allocation) ------------
__device__ __align__(256) __half g_Xt[8 * 256 * 2048];      // [bq][f][t]
__device__ __align__(256) __half g_Xnt[2 * 2048 * 1024];    // [b][t][e]
__device__ __align__(256) __half g_Wc[16 * HH];             // [aq][e][f] *1024
__device__ __align__(256) __half g_Ct[16 * HH];             // [aq][g'][g] *1024
__device__ __align__(256) float  g_Gpart[6 * 8 * 3 * 16384];// [chunk][bq][tile]
__device__ __align__(256) __half g_G[8 * HH];               // [bq][f][g]
__device__ __align__(256) __half g_T[32 * HH];              // [baq][e][g]
__device__ __align__(256) float  g_Pq[32 * HH];             // [baq][g'][e]
__device__ __align__(256) __half g_Pt[8 * HH];              // [ba][g'][e]

// ---------------- PTX helpers ------------------------------------------------
__device__ __forceinline__ uint32_t smem_u32(const void* p) {
    uint32_t a;
    asm("{ .reg .u64 t; cvta.to.shared.u64 t, %1; cvt.u32.u64 %0, t; }" : "=r"(a) : "l"(p));
    return a;
}
__device__ __forceinline__ void cpa16(uint32_t s, const void* g) {
    asm volatile("cp.async.cg.shared.global [%0], [%1], 16;" :: "r"(s), "l"(g));
}
#define CP_COMMIT() asm volatile("cp.async.commit_group;" ::: "memory")
#define CP_WAIT(n)  asm volatile("cp.async.wait_group %0;" :: "n"(n) : "memory")

#define LDSM_X4(r, addr) \
    asm volatile("ldmatrix.sync.aligned.m8n8.x4.shared.b16 {%0,%1,%2,%3}, [%4];" \
        : "=r"((r)[0]), "=r"((r)[1]), "=r"((r)[2]), "=r"((r)[3]) : "r"(addr))

#define MMA_F16(d, a, b0, b1) \
    asm volatile("mma.sync.aligned.m16n8k16.row.col.f32.f16.f16.f32 " \
        "{%0,%1,%2,%3}, {%4,%5,%6,%7}, {%8,%9}, {%0,%1,%2,%3};" \
        : "+f"((d)[0]), "+f"((d)[1]), "+f"((d)[2]), "+f"((d)[3]) \
        : "r"((a)[0]), "r"((a)[1]), "r"((a)[2]), "r"((a)[3]), "r"(b0), "r"(b1))

__device__ __forceinline__ uint2 pack4H(float4 v) {
    union { __half b[4]; uint2 u; } Hq;
    Hq.b[0] = __float2half_rn(v.x); Hq.b[1] = __float2half_rn(v.y);
    Hq.b[2] = __float2half_rn(v.z); Hq.b[3] = __float2half_rn(v.w);
    return Hq.u;
}

// ============================================================================
// 128x128 tile GEMM, 256 threads (8 warps: 4M x 2N, warp tile 32x64).
// K multiple of 64, double-buffered cp.async, single-pass fp16, fp32 accum.
// EPI 0: fp32*scale -> Cf.   EPI 1: fp16 -> Ch.
// SMEM/buffer: A 128x144B = 18432 + B 128x144B = 18432 => 36864; x2 = 73728.
// ============================================================================
#define ROWB   144
#define T_A    0
#define T_B    18432
#define BUFSZ  36864
#define SMEM_DYN (2 * BUFSZ)

template <int EPI>
__device__ __forceinline__ void gemm_body(
    const __half* __restrict__ A, int lda,
    const __half* __restrict__ B, int ldb,
    int K, float* __restrict__ Cf, __half* __restrict__ Ch, int ldc,
    float outScale)
{
    extern __shared__ char smem[];
    const uint32_t sb  = smem_u32(smem);
    const int tid  = threadIdx.x;
    const int lane = tid & 31;
    const int wid  = tid >> 5;
    const int m0   = (wid >> 1) * 32;
    const int n0   = (wid & 1) * 64;

    const uint32_t aoff = (uint32_t)(m0 + (lane & 15)) * ROWB + ((lane >> 4) << 4);
    const uint32_t boff = (uint32_t)(n0 + ((lane >> 4) << 3) + (lane & 7)) * ROWB
                        + ((lane & 8) ? 16u : 0u);

    float acc[2][8][4];
#pragma unroll
    for (int i = 0; i < 2; i++)
#pragma unroll
        for (int j = 0; j < 8; j++)
#pragma unroll
            for (int r = 0; r < 4; r++) acc[i][j][r] = 0.0f;

    auto load_chunk = [&](int c) {
        const uint32_t bo = sb + (uint32_t)(c & 1) * BUFSZ;
        const int k0 = c << 6;
#pragma unroll
        for (int i = 0; i < 4; i++) {
            int v = i * 256 + tid;
            int r = v >> 3, j = v & 7;
            uint32_t so = (uint32_t)r * ROWB + (uint32_t)j * 16;
            cpa16(bo + T_A + so, A + (size_t)r * lda + k0 + j * 8);
            cpa16(bo + T_B + so, B + (size_t)r * ldb + k0 + j * 8);
        }
    };

    const int NC = K >> 6;
    load_chunk(0);
    CP_COMMIT();

#pragma unroll 1
    for (int c = 0; c < NC; c++) {
        if (c < NC - 1) { load_chunk(c + 1); CP_COMMIT(); CP_WAIT(1); }
        else            { CP_WAIT(0); }
        __syncthreads();

        const uint32_t bo = sb + (uint32_t)(c & 1) * BUFSZ;
        const uint32_t aP = bo + T_A + aoff;
        const uint32_t bP = bo + T_B + boff;

#pragma unroll
        for (int ks = 0; ks < 4; ks++) {
            const uint32_t ko = (uint32_t)ks * 32;
            uint32_t a0[4], a1[4];
            LDSM_X4(a0, aP + ko);
            LDSM_X4(a1, aP + 16 * ROWB + ko);
            uint32_t br[4][4];
#pragma unroll
            for (int p = 0; p < 4; p++)
                LDSM_X4(br[p], bP + (uint32_t)p * 16 * ROWB + ko);
#pragma unroll
            for (int j = 0; j < 8; j++)
                MMA_F16(acc[0][j], a0, br[j >> 1][(j & 1) * 2], br[j >> 1][(j & 1) * 2 + 1]);
#pragma unroll
            for (int j = 0; j < 8; j++)
                MMA_F16(acc[1][j], a1, br[j >> 1][(j & 1) * 2], br[j >> 1][(j & 1) * 2 + 1]);
        }
        __syncthreads();
    }

    // ---- epilogue ----
    const int rr = lane >> 2;
    const int cc = (lane & 3) * 2;
#pragma unroll
    for (int i = 0; i < 2; i++) {
#pragma unroll
        for (int j = 0; j < 8; j++) {
            const int row = m0 + i * 16 + rr;
            const int col = n0 + j * 8 + cc;
            if (EPI == 0) {
                float* p = Cf + (size_t)row * ldc + col;
                *(float2*)p = make_float2(acc[i][j][0] * outScale, acc[i][j][1] * outScale);
                *(float2*)(p + (size_t)8 * ldc) =
                    make_float2(acc[i][j][2] * outScale, acc[i][j][3] * outScale);
            } else {
                *(__half2*)(Ch + (size_t)row * ldc + col) =
                    __halves2half2(__float2half_rn(acc[i][j][0]), __float2half_rn(acc[i][j][1]));
                *(__half2*)(Ch + (size_t)(row + 8) * ldc + col) =
                    __halves2half2(__float2half_rn(acc[i][j][2]), __float2half_rn(acc[i][j][3]));
            }
        }
    }
}

// ============================================================================
// fused conversion kernel: grid 6144 blocks x 256
//   [0,4096)     : hidden tile -> Xt (transposed) AND Xnt (natural), fp16
//   [4096,5120)  : Wc *1024
//   [5120,6144)  : Ct *1024 (transposed)
// ============================================================================
__global__ void k_conv(const float* __restrict__ hid,
                       const float* __restrict__ qr,
                       const float* __restrict__ cb)
{
    __shared__ float ts[32][33];
    const int blk = blockIdx.x;
    const int tid = threadIdx.x;

    if (blk < 4096) {
        int i = blk;                                     // 8 x 64 x 8
        int fb = i & 7, tb = (i >> 3) & 63, bq = i >> 9;
        int b = bq >> 2, q = bq & 3;
        int t0 = tb * 32, f0 = fb * 32;
        int tx = tid & 31, ty = tid >> 5;
#pragma unroll
        for (int r = 0; r < 4; r++) {
            int tt = t0 + ty + r * 8;
            float v = hid[(size_t)b * 2097152 + (size_t)tt * 1024 + q * 256 + f0 + tx];
            ts[ty + r * 8][tx] = v;
            g_Xnt[(size_t)b * 2097152 + (size_t)tt * 1024 + q * 256 + f0 + tx] =
                __float2half_rn(v);
        }
        __syncthreads();
#pragma unroll
        for (int r = 0; r < 4; r++) {
            int f = f0 + ty + r * 8;
            int tw = t0 + tx;
            g_Xt[(size_t)bq * 524288 + (size_t)f * 2048 + tw] =
                __float2half_rn(ts[tx][ty + r * 8]);
        }
    } else if (blk < 5120) {
        int o4 = (blk - 4096) * 256 + tid;               // 262144 float4s
        int aq = o4 >> 14;
        int rem = (o4 << 2) & 65535;
        int e = rem >> 8, f = rem & 255;
        int a = aq >> 2, q = aq & 3;
        float4 v = *(const float4*)(qr + (size_t)a * 262144 + (size_t)e * 1024 + q * 256 + f);
        v.x *= 1024.f; v.y *= 1024.f; v.z *= 1024.f; v.w *= 1024.f;
        ((uint2*)g_Wc)[o4] = pack4H(v);
    } else {
        int i = blk - 5120;                              // 8 x 8 x 16
        int gpb = i & 7, gb = (i >> 3) & 7, aq = i >> 6;
        int a = aq >> 2, q = aq & 3;
        int g0 = gb * 32, gp0 = gpb * 32;
        int tx = tid & 31, ty = tid >> 5;
#pragma unroll
        for (int r = 0; r < 4; r++) {
            int g = g0 + ty + r * 8;
            ts[ty + r * 8][tx] =
                cb[(size_t)a * 262144 + (size_t)(q * 256 + g) * 256 + gp0 + tx] * 1024.f;
        }
        __syncthreads();
#pragma unroll
        for (int r = 0; r < 4; r++) {
            int gp = gp0 + ty + r * 8;
            int gw = g0 + tx;
            g_Ct[(size_t)aq * 65536 + (size_t)gp * 256 + gw] =
                __float2half_rn(ts[tx][ty + r * 8]);
        }
    }
}

// ---- reduce Gram partials (6 chunks, 3 tiles) + mirror + fp16 ---------------
__global__ void k_reduceG()
{
    __shared__ float s[32][33];
    const int sub = blockIdx.x, t = blockIdx.y, bq = blockIdx.z;
    const int r0 = (sub >> 2) * 32, c0 = (sub & 3) * 32;
    const int tx = threadIdx.x & 31, ty = threadIdx.x >> 5;

    const int br = (t == 2) ? 128 : 0;
    const int bc = (t == 0) ? 0 : 128;
    float v[4];
#pragma unroll
    for (int k = 0; k < 4; k++) {
        const int r = r0 + ty + k * 8;
        float a = 0.f;
#pragma unroll
        for (int ch = 0; ch < 6; ch++)
            a += g_Gpart[(size_t)((ch * 8 + bq) * 3 + t) * 16384 + r * 128 + c0 + tx];
        v[k] = a;
        s[ty + k * 8][tx] = a;
    }
#pragma unroll
    for (int k = 0; k < 4; k++) {
        size_t o = (size_t)bq * 65536 + (size_t)(br + r0 + ty + k * 8) * 256 + bc + c0 + tx;
        g_G[o] = __float2half_rn(v[k]);
    }
    if (t == 1) {
        __syncthreads();
#pragma unroll
        for (int k = 0; k < 4; k++) {
            const int orow = 128 + c0 + ty + k * 8;
            const int ocol = r0 + tx;
            g_G[(size_t)bq * 65536 + (size_t)orow * 256 + ocol] =
                __float2half_rn(s[tx][ty + k * 8]);
        }
    }
}

// ---- reduce Pq^T over q, descale 2^-10, fp16 --------------------------------
__global__ void k_reduceP()
{
    int i4 = blockIdx.x * 256 + threadIdx.x;             // 131072 float4s of P^T
    int ba = i4 >> 14;
    int off = i4 & 16383;
    int b = ba >> 2, a = ba & 3;
    size_t base = (size_t)(b * 16 + a * 4) * 16384 + off;
    float4 s = make_float4(0.f, 0.f, 0.f, 0.f);
#pragma unroll
    for (int q = 0; q < 4; q++) {
        float4 v = ((const float4*)g_Pq)[base + (size_t)q * 16384];
        s.x += v.x; s.y += v.y; s.z += v.z; s.w += v.w;
    }
    const float ds = 1.0f / 1024.0f;
    s.x *= ds; s.y *= ds; s.z *= ds; s.w *= ds;
    ((uint2*)g_Pt)[i4] = pack4H(s);
}

// ============================================================================
// GEMM stage kernels (256-thread CTAs, 128x128 tiles)
// ============================================================================
__global__ void __launch_bounds__(256, 2)
k_s1()  // Gram, symmetric: grid (tile 3, chunk 6, bq 8) = 144 CTAs
{
    const int t  = blockIdx.x;                 // 0:(0,0) 1:(0,1) 2:(1,1)
    const int ch = blockIdx.y, bq = blockIdx.z;
    const int mt = (t == 2) ? 1 : 0;
    const int nt = (t == 0) ? 0 : 1;
    const int k0 = (ch < 4) ? ch * 320 : 1280 + (ch - 4) * 384;
    const int K  = (ch < 4) ? 320 : 384;

    size_t xo = (size_t)bq * 524288;
    const __half* A = g_Xt + xo + (size_t)mt * 128 * 2048 + k0;
    const __half* B = g_Xt + xo + (size_t)nt * 128 * 2048 + k0;
    float* Cf = g_Gpart + (size_t)((ch * 8 + bq) * 3 + t) * 16384;
    gemm_body<0>(A, 2048, B, 2048, K, Cf, nullptr, 128, 1.0f);
}

__global__ void __launch_bounds__(256, 2)
k_s2()  // T = Ws @ G: grid (tile 4, 1, baq 32) = 128 CTAs
{
    int mt = blockIdx.x >> 1, nt = blockIdx.x & 1;
    int baq = blockIdx.z;
    int b = baq >> 4, a = (baq >> 2) & 3, q = baq & 3;
    const __half* A = g_Wc + (size_t)(a * 4 + q) * 65536 + (size_t)mt * 128 * 256;
    const __half* B = g_G + (size_t)(b * 4 + q) * 65536 + (size_t)nt * 128 * 256;
    __half* Ch = g_T + (size_t)baq * 65536 + (size_t)mt * 128 * 256 + nt * 128;
    gemm_body<1>(A, 256, B, 256, 256, nullptr, Ch, 256, 1.0f);
}

__global__ void __launch_bounds__(256, 2)
k_s3()  // Pq^T = Cs_t @ T^T: grid (tile 4, 1, baq 32) = 128 CTAs
{
    int mt = blockIdx.x >> 1, nt = blockIdx.x & 1;
    int baq = blockIdx.z;
    int a = (baq >> 2) & 3, q = baq & 3;
    const __half* A = g_Ct + (size_t)(a * 4 + q) * 65536 + (size_t)mt * 128 * 256;
    const __half* B = g_T + (size_t)baq * 65536 + (size_t)nt * 128 * 256;
    float* Cf = g_Pq + (size_t)baq * 65536 + (size_t)mt * 128 * 256 + nt * 128;
    gemm_body<0>(A, 256, B, 256, 256, Cf, nullptr, 256, 1.0f);
}

__global__ void __launch_bounds__(256, 2)
k_s4(float* __restrict__ out)  // out = 2^-10 * X @ P: grid (tile 32, 1, ba 8)
{
    int mt = blockIdx.x >> 1, nt = blockIdx.x & 1;
    int ba = blockIdx.z;
    int b = ba >> 2, a = ba & 3;
    const __half* A = g_Xnt + (size_t)b * 2097152 + (size_t)mt * 128 * 1024 + a * 256;
    const __half* B = g_Pt + (size_t)ba * 65536 + (size_t)nt * 128 * 256;
    float* Cf = out + (size_t)b * 2097152 + (size_t)mt * 128 * 1024 + a * 256 + nt * 128;
    gemm_body<0>(A, 1024, B, 256, 256, Cf, nullptr, 1024, 1.0f / 1024.0f);
}

// ============================================================================
extern "C" void kernel_launch(void* const* d_in, const int* in_sizes, int n_in,
                              void* d_out, int out_size)
{
    const float* hidden    = (const float*)d_in[0];  // [2,2048,1024]
    const float* queries   = (const float*)d_in[1];  // [4,256,1024]
    const float* combiners = (const float*)d_in[2];  // [4,1024,256]
    float* out = (float*)d_out;
    (void)in_sizes; (void)n_in; (void)out_size;

    cudaFuncSetAttribute(k_s1, cudaFuncAttributeMaxDynamicSharedMemorySize, SMEM_DYN);
    cudaFuncSetAttribute(k_s2, cudaFuncAttributeMaxDynamicSharedMemorySize, SMEM_DYN);
    cudaFuncSetAttribute(k_s3, cudaFuncAttributeMaxDynamicSharedMemorySize, SMEM_DYN);
    cudaFuncSetAttribute(k_s4, cudaFuncAttributeMaxDynamicSharedMemorySize, SMEM_DYN);

    k_conv<<<6144, 256>>>(hidden, queries, combiners);
    k_s1<<<dim3(3, 6, 8), 256, SMEM_DYN>>>();
    k_reduceG<<<dim3(16, 3, 8), 256>>>();
    k_s2<<<dim3(4, 1, 32), 256, SMEM_DYN>>>();
    k_s3<<<dim3(4, 1, 32), 256, SMEM_DYN>>>();
    k_reduceP<<<512, 256>>>();
    k_s4<<<dim3(32, 1, 8), 256, SMEM_DYN>>>(out);
}